// round 3
// baseline (speedup 1.0000x reference)
#include <cuda_runtime.h>

// Problem constants (fixed by the reference).
#define NB 4096      // bodies
#define KB 16384     // broad-phase keep count
#define KE 4096      // exact-phase keep count
#define TPB 256

// Spatial grid: rsum <= 3.0 (radii in [0.5,1.5]); cell 3.25 guarantees any
// AABB-overlapping pair sits in adjacent cells (incl. under edge clamping,
// which only moves points inward).
#define NC 128
#define NCELLS (NC * NC)
#define CELL 3.25f
#define ORG  (-208.0f)
#define CAP  64      // per-row local candidate cap (fallback: brute scan)

// ---- device scratch (no allocations allowed) ----
__device__ int    g_cellCnt[NCELLS];
__device__ int    g_cellStart[NCELLS + 1];
__device__ int    g_cellCur[NCELLS];
__device__ int    g_bodyCell[NB];
__device__ float4 g_sbody[NB];        // sorted (x, y, r, bitcast(body idx))
__device__ int    g_cntA[NB];         // per-row AABB hit count
__device__ int    g_cntP[NB];         // per-row penetration count
__device__ int    g_allowedRow[NB];   // per-row allowed A-hits under broad cutoff
__device__ int    g_prefE[NB];        // exclusive prefix of exact candidates
__device__ int    g_prow;             // index of the (unique) partial row, -1 if none
__device__ int    g_winner[NB];       // encoded (phase*KE + slot), -1 = untouched
__device__ float  g_evx[KE];
__device__ float  g_evy[KE];

// Pinned-rounding pair predicate — bit-identical everywhere (ranks computed
// independently in count / scan / emit must agree).
__device__ __forceinline__ void pair_flags(float xi, float yi, float ri,
                                           float xj, float yj, float rj,
                                           bool self, bool& A, bool& P) {
    float dx = fabsf(__fsub_rn(xi, xj));
    float dy = fabsf(__fsub_rn(yi, yj));
    float rs = __fadd_rn(ri, rj);
    A = (dx <= rs) & (dy <= rs) & (!self);
    float d2 = __fadd_rn(__fmaf_rn(dy, dy, __fmul_rn(dx, dx)), 1e-12f);
    P = A & (d2 < __fmul_rn(rs, rs));   // pen>0 <=> rs^2 > d^2+eps (monotone)
}

// Block-wide exclusive scan over 256 ints. Contains __syncthreads.
__device__ __forceinline__ int blk_excl_scan256(int v, int* sh8, int t) {
    int lane = t & 31, w = t >> 5;
    int x = v;
    #pragma unroll
    for (int d = 1; d < 32; d <<= 1) {
        int y = __shfl_up_sync(0xffffffffu, x, d);
        if (lane >= d) x += y;
    }
    if (lane == 31) sh8[w] = x;
    __syncthreads();
    if (t < 8) {
        int s = sh8[t];
        int acc = s;
        #pragma unroll
        for (int d = 1; d < 8; d <<= 1) {
            int y = __shfl_up_sync(0xffu, acc, d);
            if (t >= d) acc += y;
        }
        sh8[t] = acc - s;
    }
    __syncthreads();
    int r = sh8[w] + x - v;
    __syncthreads();
    return r;
}

// ------------------------- K1: zero scratch --------------------------------
__global__ void k_zero() {
    int i = blockIdx.x * blockDim.x + threadIdx.x;
    for (; i < NCELLS + NB; i += gridDim.x * blockDim.x) {
        if (i < NCELLS) g_cellCnt[i] = 0;
        else            g_winner[i - NCELLS] = -1;
    }
}

// ------------------------- K2: cell histogram ------------------------------
__global__ void k_cellcount(const float* __restrict__ pos) {
    int i = blockIdx.x * blockDim.x + threadIdx.x;
    if (i >= NB) return;
    float x = pos[2 * i], y = pos[2 * i + 1];
    int cx = (int)floorf((x - ORG) / CELL);
    int cy = (int)floorf((y - ORG) / CELL);
    cx = min(max(cx, 0), NC - 1);
    cy = min(max(cy, 0), NC - 1);
    int c = cy * NC + cx;
    g_bodyCell[i] = c;
    atomicAdd(&g_cellCnt[c], 1);
}

// --------------- K3 (1 block): cell prefix scan + scatter ------------------
__global__ void __launch_bounds__(TPB) k_build(const float* __restrict__ pos,
                                               const float* __restrict__ rad) {
    __shared__ int sh8[8];
    int t = threadIdx.x;
    int c0 = t * (NCELLS / TPB);              // 64 cells / thread
    int sum = 0;
    for (int k = 0; k < NCELLS / TPB; k++) sum += g_cellCnt[c0 + k];
    int run = blk_excl_scan256(sum, sh8, t);
    for (int k = 0; k < NCELLS / TPB; k++) {
        int c = c0 + k;
        g_cellStart[c] = run;
        g_cellCur[c]   = run;
        run += g_cellCnt[c];
    }
    if (t == TPB - 1) g_cellStart[NCELLS] = run;
    __syncthreads();
    // scatter: 16 bodies per thread
    const float2* p2 = (const float2*)pos;
    for (int m = 0; m < NB / TPB; m++) {
        int i = t * (NB / TPB) + m;
        int c = g_bodyCell[i];
        int slot = atomicAdd(&g_cellCur[c], 1);
        float2 p = p2[i];
        g_sbody[slot] = make_float4(p.x, p.y, rad[i], __int_as_float(i));
    }
}

// neighbor-range iteration helper (3 contiguous spans of the sorted list).
// Variadic so commas inside the body don't split macro arguments.
#define FOR_NEIGHBORS(cell, ...)                                   \
    {                                                              \
        int cx_ = (cell) & (NC - 1), cy_ = (cell) >> 7;            \
        int cx0_ = max(cx_ - 1, 0), cx1_ = min(cx_ + 1, NC - 1);   \
        int cy0_ = max(cy_ - 1, 0), cy1_ = min(cy_ + 1, NC - 1);   \
        for (int yy_ = cy0_; yy_ <= cy1_; yy_++) {                 \
            int s_ = g_cellStart[yy_ * NC + cx0_];                 \
            int e_ = g_cellStart[yy_ * NC + cx1_ + 1];             \
            for (int k_ = s_; k_ < e_; k_++) { __VA_ARGS__ }       \
        }                                                          \
    }

// ------------------------- K4: per-row grid counts --------------------------
__global__ void __launch_bounds__(TPB) k_rowcount(const float* __restrict__ pos,
                                                  const float* __restrict__ rad) {
    int i = blockIdx.x * blockDim.x + threadIdx.x;
    if (i >= NB) return;
    float xi = pos[2 * i], yi = pos[2 * i + 1], ri = rad[i];
    int cell = g_bodyCell[i];
    int ca = 0, cp = 0;
    FOR_NEIGHBORS(cell,
        float4 b = g_sbody[k_];
        int j = __float_as_int(b.w);
        bool A; bool P;
        pair_flags(xi, yi, ri, b.x, b.y, b.z, j == i, A, P);
        ca += A; cp += P;
    )
    g_cntA[i] = ca;
    g_cntP[i] = cp;
}

// ---- K5 (1 block): broad prefix + cutoff + exact prefix + partial-row emit --
__global__ void __launch_bounds__(TPB) k_scan(const float* __restrict__ pos,
                                              const float* __restrict__ rad) {
    __shared__ int sh8[8];
    __shared__ int shProw;
    __shared__ int shPc;
    int t = threadIdx.x;
    int r0 = t * (NB / TPB);

    int cA[NB / TPB], cP[NB / TPB];
    int sum = 0;
    #pragma unroll
    for (int m = 0; m < NB / TPB; m++) {
        cA[m] = g_cntA[r0 + m];
        cP[m] = g_cntP[r0 + m];
        sum += cA[m];
    }
    if (t == 0) { shProw = -1; shPc = 0; }
    int base = blk_excl_scan256(sum, sh8, t);   // syncs publish shProw init

    int pref = base;
    #pragma unroll
    for (int m = 0; m < NB / TPB; m++) {
        int i = r0 + m;
        int allowed = KB - pref;
        if (allowed < 0) allowed = 0;
        if (allowed > cA[m]) allowed = cA[m];
        g_allowedRow[i] = allowed;
        if (pref < KB && pref + cA[m] > KB) shProw = i;
        pref += cA[m];
    }
    __syncthreads();

    int prow = shProw;
    unsigned mA = 0, mP = 0;
    int baseA = 0, allowedP = 0;
    if (prow >= 0) {
        // brute-force ordered rescan of the single partial row
        allowedP = g_allowedRow[prow];
        const float2* p2 = (const float2*)pos;
        float2 pi = p2[prow];
        float ri = rad[prow];
        int j0 = t * (NB / TPB);
        #pragma unroll
        for (int m = 0; m < NB / TPB; m++) {
            int j = j0 + m;
            float2 pj = p2[j];
            bool A; bool P;
            pair_flags(pi.x, pi.y, ri, pj.x, pj.y, rad[j], j == prow, A, P);
            mA |= (unsigned)A << m;
            mP |= (unsigned)P << m;
        }
        baseA = blk_excl_scan256(__popc(mA), sh8, t);
        int cnt = 0;
        #pragma unroll
        for (int m = 0; m < NB / TPB; m++) {
            if ((mP >> m) & 1u) {
                int ar = baseA + __popc(mA & ((1u << m) - 1u));
                if (ar < allowedP) cnt++;
            }
        }
        cnt = __reduce_add_sync(0xffffffffu, cnt);
        if ((t & 31) == 0) atomicAdd(&shPc, cnt);
        __syncthreads();
    }
    int pc = (prow >= 0) ? shPc : 0;

    // exact-candidate exclusive prefix per row
    int cC[NB / TPB];
    int sumC = 0;
    pref = base;
    #pragma unroll
    for (int m = 0; m < NB / TPB; m++) {
        int c;
        if (pref + cA[m] <= KB)      c = cP[m];
        else if (pref >= KB)         c = 0;
        else                         c = pc;
        cC[m] = c;
        sumC += c;
        pref += cA[m];
    }
    int baseC = blk_excl_scan256(sumC, sh8, t);
    #pragma unroll
    for (int m = 0; m < NB / TPB; m++) {
        g_prefE[r0 + m] = baseC;
        baseC += cC[m];
    }
    __syncthreads();
    if (t == 0) g_prow = prow;

    // emit the partial row's entries here (block-parallel, ordered)
    if (prow >= 0) {
        unsigned mC = 0;
        #pragma unroll
        for (int m = 0; m < NB / TPB; m++) {
            if ((mP >> m) & 1u) {
                int ar = baseA + __popc(mA & ((1u << m) - 1u));
                if (ar < allowedP) mC |= 1u << m;
            }
        }
        int slotBase = g_prefE[prow] + blk_excl_scan256(__popc(mC), sh8, t);
        const float2* p2 = (const float2*)pos;
        float2 pi = p2[prow];
        float ri = rad[prow];
        unsigned mm = mC;
        int j0 = t * (NB / TPB);
        while (mm) {
            int m = __ffs(mm) - 1;
            mm &= mm - 1;
            int slot = slotBase++;
            if (slot < KE) {
                int j = j0 + m;
                float2 pj = p2[j];
                float dvx = __fsub_rn(pi.x, pj.x);
                float dvy = __fsub_rn(pi.y, pj.y);
                float rs  = __fadd_rn(ri, rad[j]);
                float d2  = __fadd_rn(__fmaf_rn(dvy, dvy, __fmul_rn(dvx, dvx)), 1e-12f);
                float dist = __fsqrt_rn(d2);
                float s = __fdiv_rn(__fsub_rn(rs, dist), dist);
                g_evx[slot] = __fmul_rn(dvx, s);
                g_evy[slot] = __fmul_rn(dvy, s);
                atomicMax(&g_winner[prow], slot);
                atomicMax(&g_winner[j],    slot + KE);
            }
        }
    }
}

// ------------------------- K6: emit (per body) -------------------------------
__global__ void __launch_bounds__(TPB) k_emit(const float* __restrict__ pos,
                                              const float* __restrict__ rad) {
    int i = blockIdx.x * blockDim.x + threadIdx.x;
    if (i >= NB) return;
    if (i == g_prow) return;                    // handled in k_scan
    int allowed = g_allowedRow[i];
    if (allowed == 0) return;                   // row beyond broad cutoff (or empty)
    int baseE = g_prefE[i];
    if (baseE >= KE) return;
    int cp = g_cntP[i];
    if (cp == 0) return;

    float xi = pos[2 * i], yi = pos[2 * i + 1], ri = rad[i];

    if (cp <= CAP) {
        int jl[CAP];
        int k = 0;
        int cell = g_bodyCell[i];
        FOR_NEIGHBORS(cell,
            float4 b = g_sbody[k_];
            int j = __float_as_int(b.w);
            bool A; bool P;
            pair_flags(xi, yi, ri, b.x, b.y, b.z, j == i, A, P);
            if (P) jl[k++] = j;
        )
        // insertion sort ascending j (restores row-major within-row order)
        for (int a = 1; a < k; a++) {
            int v = jl[a];
            int b = a - 1;
            while (b >= 0 && jl[b] > v) { jl[b + 1] = jl[b]; b--; }
            jl[b + 1] = v;
        }
        for (int a = 0; a < k; a++) {
            int slot = baseE + a;
            if (slot >= KE) break;
            int j = jl[a];
            float xj = pos[2 * j], yj = pos[2 * j + 1];
            float dvx = __fsub_rn(xi, xj);
            float dvy = __fsub_rn(yi, yj);
            float rs  = __fadd_rn(ri, rad[j]);
            float d2  = __fadd_rn(__fmaf_rn(dvy, dvy, __fmul_rn(dvx, dvx)), 1e-12f);
            float dist = __fsqrt_rn(d2);
            float s = __fdiv_rn(__fsub_rn(rs, dist), dist);
            g_evx[slot] = __fmul_rn(dvx, s);
            g_evy[slot] = __fmul_rn(dvy, s);
            atomicMax(&g_winner[i], slot);
            atomicMax(&g_winner[j], slot + KE);
        }
    } else {
        // overflow fallback: brute-force ordered scan (row fully under cutoff
        // here, so every P-hit is allowed)
        int rank = 0;
        for (int j = 0; j < NB; j++) {
            float xj = pos[2 * j], yj = pos[2 * j + 1], rj = rad[j];
            bool A; bool P;
            pair_flags(xi, yi, ri, xj, yj, rj, j == i, A, P);
            if (P) {
                int slot = baseE + rank;
                rank++;
                if (slot < KE) {
                    float dvx = __fsub_rn(xi, xj);
                    float dvy = __fsub_rn(yi, yj);
                    float rs  = __fadd_rn(ri, rj);
                    float d2  = __fadd_rn(__fmaf_rn(dvy, dvy, __fmul_rn(dvx, dvx)), 1e-12f);
                    float dist = __fsqrt_rn(d2);
                    float s = __fdiv_rn(__fsub_rn(rs, dist), dist);
                    g_evx[slot] = __fmul_rn(dvx, s);
                    g_evy[slot] = __fmul_rn(dvy, s);
                    atomicMax(&g_winner[i], slot);
                    atomicMax(&g_winner[j], slot + KE);
                }
            }
        }
    }
}

// ------------------------- K7: resolve ---------------------------------------
__global__ void k_resolve(const float* __restrict__ pos, float* __restrict__ out) {
    int bdy = blockIdx.x * blockDim.x + threadIdx.x;
    if (bdy >= NB) return;
    float x = pos[2 * bdy];
    float y = pos[2 * bdy + 1];
    int w = g_winner[bdy];
    if (w >= KE) {
        int k = w - KE;
        x = __fsub_rn(x, __fmul_rn(0.5f, g_evx[k]));
        y = __fsub_rn(y, __fmul_rn(0.5f, g_evy[k]));
    } else if (w >= 0) {
        x = __fadd_rn(x, __fmul_rn(0.5f, g_evx[w]));
        y = __fadd_rn(y, __fmul_rn(0.5f, g_evy[w]));
    }
    out[2 * bdy]     = x;
    out[2 * bdy + 1] = y;
}

extern "C" void kernel_launch(void* const* d_in, const int* in_sizes, int n_in,
                              void* d_out, int out_size) {
    const float* pos;
    const float* rad;
    if (in_sizes[0] == 2 * NB) { pos = (const float*)d_in[0]; rad = (const float*)d_in[1]; }
    else                       { pos = (const float*)d_in[1]; rad = (const float*)d_in[0]; }
    float* out = (float*)d_out;

    k_zero      <<<80, 256>>>();
    k_cellcount <<<16, TPB>>>(pos);
    k_build     <<<1,  TPB>>>(pos, rad);
    k_rowcount  <<<16, TPB>>>(pos, rad);
    k_scan      <<<1,  TPB>>>(pos, rad);
    k_emit      <<<16, TPB>>>(pos, rad);
    k_resolve   <<<16, TPB>>>(pos, out);
}